// round 3
// baseline (speedup 1.0000x reference)
#include <cuda_runtime.h>

#define BB 8
#define NN 2048
#define ITERS 50
#define ROWS 64

// scratch (allocation-free rule: __device__ global)
__device__ float gMinv[BB * 128 * 128];   // 512 KB

// ---- packed f32x2 helpers (ptxas won't emit FFMA2 from C++) ----
__device__ __forceinline__ unsigned long long ffma2(unsigned long long a,
                                                    unsigned long long b,
                                                    unsigned long long c) {
    unsigned long long d;
    asm("fma.rn.f32x2 %0, %1, %2, %3;" : "=l"(d) : "l"(a), "l"(b), "l"(c));
    return d;
}
__device__ __forceinline__ unsigned long long pack2(float x) {
    union { unsigned long long u; float2 f; } c;
    c.f = make_float2(x, x);
    return c.u;
}
__device__ __forceinline__ float2 unpack2(unsigned long long v) {
    union { unsigned long long u; float2 f; } c;
    c.u = v;
    return c.f;
}

// ============================================================================
// Kernel 1: Minv = (I + E)^-1 via 7-step Neumann-Horner, E = (2/m^2) V V^T.
// ||E|| <= ~0.0655 -> truncation error ||E||^8/(1-||E||) ~ 3e-10 (<< fp32 eps).
// grid 8 (1 CTA/batch) x 1024 threads.
// smem: sVt[128*132] ([d][m], padded) + sEA[128*129] (A-layout) + sY[128*128]
// ============================================================================
__global__ __launch_bounds__(1024, 1) void k_minv(const float* __restrict__ gV) {
    extern __shared__ float smem[];
    float* sVt = smem;                  // 128*132
    float* sEA = smem + 128 * 132;      // 128*129 (stride 129: conflict-free scalar col reads)
    float* sY  = sEA + 128 * 129;       // 128*128 (stride 128: aligned LDS.128 broadcast)
    const int b = blockIdx.x;
    const int t = threadIdx.x;

    // transposed load: V[m][d] -> sVt[d][m] (stride 132: 16B-aligned rows, 4-way STS conflict ok)
    for (int idx = t; idx < 16384; idx += 1024) {
        int m = idx >> 7, d = idx & 127;
        sVt[d * 132 + m] = gV[b * 16384 + idx];
    }
    __syncthreads();

    const int r = t & 127;
    const int i0 = (t >> 7) * 16;

    // E[r][i] = (1/8192) * sum_d Vt[d][r] * Vt[d][i]
    {
        unsigned long long acc[8];
#pragma unroll
        for (int e = 0; e < 8; e++) acc[e] = 0ULL;
#pragma unroll 8
        for (int d = 0; d < 128; d++) {
            unsigned long long a2 = pack2(sVt[d * 132 + r]);
            const ulonglong2* pm = (const ulonglong2*)(sVt + d * 132 + i0);
#pragma unroll
            for (int q = 0; q < 4; q++) {
                ulonglong2 mv = pm[q];
                acc[2 * q]     = ffma2(mv.x, a2, acc[2 * q]);
                acc[2 * q + 1] = ffma2(mv.y, a2, acc[2 * q + 1]);
            }
        }
        const float sc = 1.0f / 8192.0f;
#pragma unroll
        for (int e = 0; e < 8; e++) {
            float2 v = unpack2(acc[e]);
            sEA[r * 129 + i0 + 2 * e]     = sc * v.x;
            sEA[r * 129 + i0 + 2 * e + 1] = sc * v.y;
        }
    }
    __syncthreads();

    // Y = I - E
    for (int idx = t; idx < 16384; idx += 1024) {
        int i = idx >> 7, j = idx & 127;
        sY[idx] = ((i == j) ? 1.0f : 0.0f) - sEA[i * 129 + j];
    }
    __syncthreads();

    // 7x: Y <- I - E*Y   (final degree-8 Neumann polynomial... degree 1+7 = 8 terms)
    for (int step = 0; step < 7; step++) {
        unsigned long long acc[8];
#pragma unroll
        for (int e = 0; e < 8; e++) acc[e] = 0ULL;
#pragma unroll 8
        for (int d = 0; d < 128; d++) {
            unsigned long long a2 = pack2(sEA[r * 129 + d]);
            const ulonglong2* pm = (const ulonglong2*)(sY + d * 128 + i0);
#pragma unroll
            for (int q = 0; q < 4; q++) {
                ulonglong2 mv = pm[q];
                acc[2 * q]     = ffma2(mv.x, a2, acc[2 * q]);
                acc[2 * q + 1] = ffma2(mv.y, a2, acc[2 * q + 1]);
            }
        }
        __syncthreads();   // all reads of sY complete before in-place overwrite
#pragma unroll
        for (int e = 0; e < 8; e++) {
            float2 v = unpack2(acc[e]);
            int c0 = i0 + 2 * e;
            sY[r * 128 + c0]     = ((r == c0)     ? 1.0f : 0.0f) - v.x;
            sY[r * 128 + c0 + 1] = ((r == c0 + 1) ? 1.0f : 0.0f) - v.y;
        }
        __syncthreads();
    }

    for (int idx = t; idx < 16384; idx += 1024)
        gMinv[b * 16384 + idx] = sY[idx];
}

// ============================================================================
// Kernel 2 (fused): P prep + 50 ADMM iterations + threshold + output GEMM.
// grid 256 (b*32 + tile), 512 threads. Thread owns (row r, 16 i's).
// z, u, P live in registers for all 50 iterations.
// smem: sMat[128*132] (Vt for P phase / Minv / V) + sRhs[64*129] + sCnt[512]
// ============================================================================
__global__ __launch_bounds__(512, 1) void k_admm(const float* __restrict__ gQ,
                                                 const float* __restrict__ gV,
                                                 float* __restrict__ gOut) {
    extern __shared__ float smem[];
    float* sMat = smem;                    // 128*132 region (stride 132 in P phase, 128 after)
    float* sRhs = smem + 128 * 132;        // 64*129
    float* sCnt = sRhs + ROWS * 129;       // 512
    const int blk = blockIdx.x;
    const int b = blk >> 5;
    const int row0 = (blk & 31) * ROWS;
    const int t = threadIdx.x;
    const int r = t & 63;
    const int iq = t >> 6;                 // 0..7
    const int i0 = iq * 16;

    // ---- Phase P: load Vt (transposed, stride 132) + Q rows, compute P in regs ----
    for (int idx = t; idx < 16384; idx += 512) {
        int m = idx >> 7, d = idx & 127;
        sMat[d * 132 + m] = gV[b * 16384 + idx];
    }
    for (int idx = t; idx < ROWS * 128; idx += 512) {
        int rl = idx >> 7, d = idx & 127;
        sRhs[rl * 129 + d] = gQ[(b * NN + row0 + rl) * 128 + d];
    }
    __syncthreads();

    float z[16], u[16], Pr[16];
    {
        unsigned long long acc[8];
#pragma unroll
        for (int e = 0; e < 8; e++) acc[e] = 0ULL;
#pragma unroll 8
        for (int d = 0; d < 128; d++) {
            unsigned long long q2 = pack2(sRhs[r * 129 + d]);
            const ulonglong2* pm = (const ulonglong2*)(sMat + d * 132 + i0);
#pragma unroll
            for (int q = 0; q < 4; q++) {
                ulonglong2 mv = pm[q];
                acc[2 * q]     = ffma2(mv.x, q2, acc[2 * q]);
                acc[2 * q + 1] = ffma2(mv.y, q2, acc[2 * q + 1]);
            }
        }
        const float cP = -2.0f / 128.0f;
        const float cL = 0.1f / 128.0f;
#pragma unroll
        for (int e = 0; e < 8; e++) {
            float2 v = unpack2(acc[e]);
            Pr[2 * e]     = cP * v.x + cL;
            Pr[2 * e + 1] = cP * v.y + cL;
        }
    }
#pragma unroll
    for (int e = 0; e < 16; e++) { z[e] = 0.0f; u[e] = 0.0f; }
    __syncthreads();   // P-phase reads of sMat done

    // ---- load Minv (stride 128) ----
    for (int idx = t; idx < 16384; idx += 512)
        sMat[idx] = gMinv[b * 16384 + idx];

    // ---- 50 ADMM iterations ----
    for (int it = 0; it < ITERS; it++) {
#pragma unroll
        for (int e = 0; e < 16; e++)
            sRhs[r * 129 + i0 + e] = (z[e] - u[e]) - Pr[e];   // RHO = 1
        __syncthreads();   // also covers Minv load on iter 0

        unsigned long long acc[8];
#pragma unroll
        for (int e = 0; e < 8; e++) acc[e] = 0ULL;
#pragma unroll 8
        for (int j = 0; j < 128; j++) {
            unsigned long long rv2 = pack2(sRhs[r * 129 + j]);
            const ulonglong2* pm = (const ulonglong2*)(sMat + j * 128 + i0);
#pragma unroll
            for (int q = 0; q < 4; q++) {
                ulonglong2 mv = pm[q];
                acc[2 * q]     = ffma2(mv.x, rv2, acc[2 * q]);
                acc[2 * q + 1] = ffma2(mv.y, rv2, acc[2 * q + 1]);
            }
        }
        __syncthreads();   // all matmul reads of sRhs done before next-iter write

#pragma unroll
        for (int e = 0; e < 8; e++) {
            float2 xv = unpack2(acc[e]);
            float xu0 = xv.x + u[2 * e];
            float zn0 = fminf(fmaxf(xu0, 0.0f), 1.0f);
            u[2 * e] = xu0 - zn0;
            z[2 * e] = zn0;
            float xu1 = xv.y + u[2 * e + 1];
            float zn1 = fminf(fmaxf(xu1, 0.0f), 1.0f);
            u[2 * e + 1] = xu1 - zn1;
            z[2 * e + 1] = zn1;
        }
    }

    // ---- epilogue: sMat <- V (row-major), threshold + counts ----
    for (int idx = t; idx < 16384; idx += 512)
        sMat[idx] = gV[b * 16384 + idx];
    float cp = 0.0f;
#pragma unroll
    for (int e = 0; e < 16; e++) cp += (z[e] > 0.5f) ? 1.0f : 0.0f;
    sCnt[r * 8 + iq] = cp;
    __syncthreads();

    float cnt = 0.0f;
#pragma unroll
    for (int k = 0; k < 8; k++) cnt += sCnt[r * 8 + k];
    float inv = 1.0f / (128.0f * (cnt + 1e-10f));   // folds V/m scaling
#pragma unroll
    for (int e = 0; e < 16; e++)
        sRhs[r * 129 + i0 + e] = (z[e] > 0.5f) ? inv : 0.0f;
    __syncthreads();

    // out[r][i0..i0+15] = sum_m coeff[r][m] * V[m][d]
    unsigned long long acc[8];
#pragma unroll
    for (int e = 0; e < 8; e++) acc[e] = 0ULL;
#pragma unroll 8
    for (int mi = 0; mi < 128; mi++) {
        unsigned long long c2 = pack2(sRhs[r * 129 + mi]);
        const ulonglong2* pm = (const ulonglong2*)(sMat + mi * 128 + i0);
#pragma unroll
        for (int q = 0; q < 4; q++) {
            ulonglong2 mv = pm[q];
            acc[2 * q]     = ffma2(mv.x, c2, acc[2 * q]);
            acc[2 * q + 1] = ffma2(mv.y, c2, acc[2 * q + 1]);
        }
    }
    float* op = gOut + (b * NN + row0 + r) * 128 + i0;
#pragma unroll
    for (int q = 0; q < 4; q++) {
        ulonglong2 v = *(ulonglong2*)&acc[2 * q];
        float2 a = unpack2(v.x);
        float2 c = unpack2(v.y);
        ((float4*)op)[q] = make_float4(a.x, a.y, c.x, c.y);
    }
}

// ============================================================================

extern "C" void kernel_launch(void* const* d_in, const int* in_sizes, int n_in,
                              void* d_out, int out_size) {
    const float* gQ = (const float*)d_in[0];
    const float* gV = (const float*)d_in[1];
    if (n_in >= 2 && in_sizes[0] == BB * 128 * 128 && in_sizes[1] == BB * NN * 128) {
        gV = (const float*)d_in[0];
        gQ = (const float*)d_in[1];
    }
    float* out = (float*)d_out;

    const int SMEM_MINV = (128 * 132 + 128 * 129 + 128 * 128) * 4;   // 199168
    const int SMEM_ADMM = (128 * 132 + ROWS * 129 + 512) * 4;        // 102656

    cudaFuncSetAttribute(k_minv, cudaFuncAttributeMaxDynamicSharedMemorySize, SMEM_MINV);
    cudaFuncSetAttribute(k_admm, cudaFuncAttributeMaxDynamicSharedMemorySize, SMEM_ADMM);

    k_minv<<<BB, 1024, SMEM_MINV>>>(gV);
    k_admm<<<BB * (NN / ROWS), 512, SMEM_ADMM>>>(gQ, gV, out);
}

// round 5
// speedup vs baseline: 3.6474x; 3.6474x over previous
#include <cuda_runtime.h>
#include <cuda_bf16.h>
#include <cstdint>

#define BB 8
#define NN 2048
#define ITERS 50

// ---- device scratch (no allocs allowed) ----
__device__ float gE[BB * 16384], gE2[BB * 16384], gE4[BB * 16384], gTT[BB * 16384];
__device__ __nv_bfloat16 gW1[BB * 16384], gW2[BB * 16384];

// ---- f32x2 helpers (prep kernels) ----
__device__ __forceinline__ unsigned long long ffma2(unsigned long long a,
                                                    unsigned long long b,
                                                    unsigned long long c) {
    unsigned long long d;
    asm("fma.rn.f32x2 %0, %1, %2, %3;" : "=l"(d) : "l"(a), "l"(b), "l"(c));
    return d;
}
__device__ __forceinline__ unsigned long long pack2(float x) {
    union { unsigned long long u; float2 f; } c; c.f = make_float2(x, x); return c.u;
}
__device__ __forceinline__ float2 unpack2(unsigned long long v) {
    union { unsigned long long u; float2 f; } c; c.u = v; return c.f;
}

// ---- HMMA wrapper: m16n8k16 bf16 -> f32 (sm_80+, no arch-specific target) ----
__device__ __forceinline__ void mma_bf16(float c[4],
                                         uint32_t a0, uint32_t a1, uint32_t a2, uint32_t a3,
                                         uint32_t b0, uint32_t b1) {
    asm volatile(
        "mma.sync.aligned.m16n8k16.row.col.f32.bf16.bf16.f32 "
        "{%0,%1,%2,%3}, {%4,%5,%6,%7}, {%8,%9}, {%0,%1,%2,%3};"
        : "+f"(c[0]), "+f"(c[1]), "+f"(c[2]), "+f"(c[3])
        : "r"(a0), "r"(a1), "r"(a2), "r"(a3), "r"(b0), "r"(b1));
}

// split a float pair into bf16 hi + bf16 lo words (x in low half, y in high)
__device__ __forceinline__ void split2(float x, float y, uint32_t& hi, uint32_t& lo) {
    __nv_bfloat162 h = __float22bfloat162_rn(make_float2(x, y));
    float2 hb = __bfloat1622float2(h);
    __nv_bfloat162 l = __float22bfloat162_rn(make_float2(x - hb.x, y - hb.y));
    hi = *(uint32_t*)&h;
    lo = *(uint32_t*)&l;
}

// ============================================================================
// kE: E = (1/8192) V V^T.   grid 32 (b*4 + 32-row slice) x 256 thr.
// ============================================================================
__global__ __launch_bounds__(256, 1) void kE(const float* __restrict__ gV) {
    extern __shared__ float sm[];
    float* sVt = sm;                         // [128][132]
    const int b = blockIdx.x >> 2, r0 = (blockIdx.x & 3) * 32;
    const int t = threadIdx.x;
    for (int idx = t; idx < 16384; idx += 256) {
        int m = idx >> 7, d = idx & 127;
        sVt[d * 132 + m] = gV[b * 16384 + idx];
    }
    __syncthreads();
    const int rl = t & 31, r = r0 + rl, i0 = (t >> 5) * 16;
    unsigned long long acc[8];
#pragma unroll
    for (int e = 0; e < 8; e++) acc[e] = 0ULL;
#pragma unroll 8
    for (int d = 0; d < 128; d++) {
        unsigned long long a2 = pack2(sVt[d * 132 + r]);
        const ulonglong2* pm = (const ulonglong2*)(sVt + d * 132 + i0);
#pragma unroll
        for (int q = 0; q < 4; q++) {
            ulonglong2 mv = pm[q];
            acc[2 * q]     = ffma2(mv.x, a2, acc[2 * q]);
            acc[2 * q + 1] = ffma2(mv.y, a2, acc[2 * q + 1]);
        }
    }
    const float sc = 1.0f / 8192.0f;
#pragma unroll
    for (int e = 0; e < 8; e++) {
        float2 v = unpack2(acc[e]);
        gE[b * 16384 + r * 128 + i0 + 2 * e]     = sc * v.x;
        gE[b * 16384 + r * 128 + i0 + 2 * e + 1] = sc * v.y;
    }
}

// ============================================================================
// kMM: C = A*B (+A+B if mode).   grid 32 x 256.
// ============================================================================
__global__ __launch_bounds__(256, 1) void kMM(const float* __restrict__ A,
                                              const float* __restrict__ B,
                                              float* __restrict__ C, int mode) {
    extern __shared__ float sm[];
    float* sA = sm;                 // [32][129]
    float* sB = sm + 32 * 129;      // [128][128]
    const int b = blockIdx.x >> 2, r0 = (blockIdx.x & 3) * 32;
    const int t = threadIdx.x;
    for (int idx = t; idx < 4096; idx += 256) {
        int row = idx >> 7, j = idx & 127;
        sA[row * 129 + j] = A[b * 16384 + (r0 + row) * 128 + j];
    }
    for (int idx = t; idx < 16384; idx += 256) sB[idx] = B[b * 16384 + idx];
    __syncthreads();
    const int rl = t & 31, r = r0 + rl, i0 = (t >> 5) * 16;
    unsigned long long acc[8];
#pragma unroll
    for (int e = 0; e < 8; e++) acc[e] = 0ULL;
#pragma unroll 8
    for (int j = 0; j < 128; j++) {
        unsigned long long a2 = pack2(sA[rl * 129 + j]);
        const ulonglong2* pm = (const ulonglong2*)(sB + j * 128 + i0);
#pragma unroll
        for (int q = 0; q < 4; q++) {
            ulonglong2 mv = pm[q];
            acc[2 * q]     = ffma2(mv.x, a2, acc[2 * q]);
            acc[2 * q + 1] = ffma2(mv.y, a2, acc[2 * q + 1]);
        }
    }
#pragma unroll
    for (int e = 0; e < 8; e++) {
        float2 v = unpack2(acc[e]);
        int c0 = i0 + 2 * e;
        float o0 = v.x, o1 = v.y;
        if (mode) {
            o0 += sA[rl * 129 + c0]     + sB[r * 128 + c0];
            o1 += sA[rl * 129 + c0 + 1] + sB[r * 128 + c0 + 1];
        }
        C[b * 16384 + r * 128 + c0]     = o0;
        C[b * 16384 + r * 128 + c0 + 1] = o1;
    }
}

// ============================================================================
// kW: W = TT - E - E*TT  (= Minv - I, err ~3e-10); write bf16 hi/lo, plain
// row-major [128][128].  grid 32 x 256.
// ============================================================================
__global__ __launch_bounds__(256, 1) void kW() {
    extern __shared__ float sm[];
    float* sA = sm;                 // E slice [32][129]
    float* sB = sm + 32 * 129;      // TT [128][128]
    const int b = blockIdx.x >> 2, r0 = (blockIdx.x & 3) * 32;
    const int t = threadIdx.x;
    for (int idx = t; idx < 4096; idx += 256) {
        int row = idx >> 7, j = idx & 127;
        sA[row * 129 + j] = gE[b * 16384 + (r0 + row) * 128 + j];
    }
    for (int idx = t; idx < 16384; idx += 256) sB[idx] = gTT[b * 16384 + idx];
    __syncthreads();
    const int rl = t & 31, r = r0 + rl, k0 = (t >> 5) * 16;
    unsigned long long acc[8];
#pragma unroll
    for (int e = 0; e < 8; e++) acc[e] = 0ULL;
#pragma unroll 8
    for (int j = 0; j < 128; j++) {
        unsigned long long a2 = pack2(sA[rl * 129 + j]);
        const ulonglong2* pm = (const ulonglong2*)(sB + j * 128 + k0);
#pragma unroll
        for (int q = 0; q < 4; q++) {
            ulonglong2 mv = pm[q];
            acc[2 * q]     = ffma2(mv.x, a2, acc[2 * q]);
            acc[2 * q + 1] = ffma2(mv.y, a2, acc[2 * q + 1]);
        }
    }
    uint32_t* o1 = (uint32_t*)gW1 + b * 8192;
    uint32_t* o2 = (uint32_t*)gW2 + b * 8192;
#pragma unroll
    for (int e = 0; e < 8; e++) {
        float2 m1 = unpack2(acc[e]);
        int k = k0 + 2 * e;
        float wx = sB[r * 128 + k]     - sA[rl * 129 + k]     - m1.x;
        float wy = sB[r * 128 + k + 1] - sA[rl * 129 + k + 1] - m1.y;
        uint32_t hi, lo;
        split2(wx, wy, hi, lo);
        o1[r * 64 + (k >> 1)] = hi;
        o2[r * 64 + (k >> 1)] = lo;
    }
}

// ============================================================================
// k_admm: fused P-prep + 50 HMMA ADMM iterations + epilogue.
// grid 128 (b*16 + 128-row tile) x 512 threads (16 warps: 8 m-tiles x 2 n-halves).
// Per warp: C = m16 x n64 (8 n-tiles); z,u live in C-fragment layout registers.
// x = rhs + W*rhs, 3-term bf16 split (AhiW1 + AloW1 + AhiW2); W symmetric so
// B fragments load directly from row-major W tiles.
// ============================================================================
#define S136 136                 // bf16 tile row stride (conflict-free frag loads)
#define SM_RH 0                  // rhs hi  [128][136] bf16 = 34816 B
#define SM_RL 34816              // rhs lo
#define SM_W1 69632              // W hi    (Vhi in prep / Vt hi in epilogue)
#define SM_W2 104448             // W lo
#define SM_P  139264             // P f32 [128][132] = 67584 B
#define SM_CNT 206848            // f32 [128][8] = 4096 B
#define SMEM_ADMM 210944

__global__ __launch_bounds__(512, 1) void k_admm(const float* __restrict__ gQ,
                                                 const float* __restrict__ gV,
                                                 float* __restrict__ gOut) {
    extern __shared__ char smem[];
    __nv_bfloat16* rhB = (__nv_bfloat16*)(smem + SM_RH);
    __nv_bfloat16* rlB = (__nv_bfloat16*)(smem + SM_RL);
    __nv_bfloat16* w1B = (__nv_bfloat16*)(smem + SM_W1);
    __nv_bfloat16* w2B = (__nv_bfloat16*)(smem + SM_W2);
    float* sP   = (float*)(smem + SM_P);
    float* sCnt = (float*)(smem + SM_CNT);

    const int t = threadIdx.x;
    const int lane = t & 31, w = t >> 5;
    const int gid = lane >> 2, tig = lane & 3;
    const int m0 = (w & 7) * 16, n0 = (w >> 3) * 64;
    const int r0 = m0 + gid, r1 = r0 + 8;
    const int b = blockIdx.x >> 4, row0 = (blockIdx.x & 15) * 128;
    const float* Vb = gV + b * 16384;
    const float* Qb = gQ + (size_t)(b * NN + row0) * 128;

    // ---- prologue: Q split -> rhs tiles; V split -> W tiles ([m][d]) ----
    for (int idx = t; idx < 8192; idx += 512) {
        int row = idx >> 6, c2 = (idx & 63) * 2;
        float2 q = *(const float2*)(Qb + row * 128 + c2);
        uint32_t hi, lo;
        split2(q.x, q.y, hi, lo);
        *(uint32_t*)(rhB + row * S136 + c2) = hi;
        *(uint32_t*)(rlB + row * S136 + c2) = lo;
        float2 v = *(const float2*)(Vb + row * 128 + c2);
        split2(v.x, v.y, hi, lo);
        *(uint32_t*)(w1B + row * S136 + c2) = hi;
        *(uint32_t*)(w2B + row * S136 + c2) = lo;
    }
    __syncthreads();

    // ---- P = -(2/m) Q V^T + lambda/m   (3-term MMA: QhVh + QlVh + QhVl) ----
    {
        float acc[8][4];
#pragma unroll
        for (int nt = 0; nt < 8; nt++)
#pragma unroll
            for (int j = 0; j < 4; j++) acc[nt][j] = 0.0f;
#pragma unroll
        for (int k0 = 0; k0 < 8; k0++) {
            int ka = k0 * 16 + 2 * tig;
            uint32_t ah0 = *(uint32_t*)(rhB + r0 * S136 + ka);
            uint32_t ah1 = *(uint32_t*)(rhB + r1 * S136 + ka);
            uint32_t ah2 = *(uint32_t*)(rhB + r0 * S136 + ka + 8);
            uint32_t ah3 = *(uint32_t*)(rhB + r1 * S136 + ka + 8);
            uint32_t al0 = *(uint32_t*)(rlB + r0 * S136 + ka);
            uint32_t al1 = *(uint32_t*)(rlB + r1 * S136 + ka);
            uint32_t al2 = *(uint32_t*)(rlB + r0 * S136 + ka + 8);
            uint32_t al3 = *(uint32_t*)(rlB + r1 * S136 + ka + 8);
#pragma unroll
            for (int nt = 0; nt < 8; nt++) {
                int bn = n0 + nt * 8 + gid;
                uint32_t b0 = *(uint32_t*)(w1B + bn * S136 + ka);
                uint32_t b1 = *(uint32_t*)(w1B + bn * S136 + ka + 8);
                mma_bf16(acc[nt], ah0, ah1, ah2, ah3, b0, b1);
                mma_bf16(acc[nt], al0, al1, al2, al3, b0, b1);
                uint32_t c0 = *(uint32_t*)(w2B + bn * S136 + ka);
                uint32_t c1 = *(uint32_t*)(w2B + bn * S136 + ka + 8);
                mma_bf16(acc[nt], ah0, ah1, ah2, ah3, c0, c1);
            }
        }
        const float cP = -2.0f / 128.0f, cL = 0.1f / 128.0f;
#pragma unroll
        for (int nt = 0; nt < 8; nt++) {
            int c = n0 + nt * 8 + 2 * tig;
            *(float2*)(sP + r0 * 132 + c) = make_float2(cP * acc[nt][0] + cL, cP * acc[nt][1] + cL);
            *(float2*)(sP + r1 * 132 + c) = make_float2(cP * acc[nt][2] + cL, cP * acc[nt][3] + cL);
        }
    }
    __syncthreads();   // V-tile reads done; safe to overwrite with W

    // ---- load W bf16 hi/lo into W tiles ----
    {
        const uint32_t* w1g = (const uint32_t*)gW1 + b * 8192;
        const uint32_t* w2g = (const uint32_t*)gW2 + b * 8192;
        for (int idx = t; idx < 8192; idx += 512) {
            int row = idx >> 6, cw = idx & 63;
            *(uint32_t*)(w1B + row * S136 + cw * 2) = w1g[row * 64 + cw];
            *(uint32_t*)(w2B + row * S136 + cw * 2) = w2g[row * 64 + cw];
        }
    }

    float z[32], u[32];
#pragma unroll
    for (int e = 0; e < 32; e++) { z[e] = 0.0f; u[e] = 0.0f; }

    // ---- 50 ADMM iterations ----
    for (int it = 0; it < ITERS; it++) {
        // write rhs = z - u - P as bf16 hi/lo tiles (own elements only)
#pragma unroll
        for (int nt = 0; nt < 8; nt++) {
            int c = n0 + nt * 8 + 2 * tig;
            float2 p0 = *(float2*)(sP + r0 * 132 + c);
            float2 p1 = *(float2*)(sP + r1 * 132 + c);
            uint32_t hi, lo;
            split2(z[4 * nt] - u[4 * nt] - p0.x, z[4 * nt + 1] - u[4 * nt + 1] - p0.y, hi, lo);
            *(uint32_t*)(rhB + r0 * S136 + c) = hi;
            *(uint32_t*)(rlB + r0 * S136 + c) = lo;
            split2(z[4 * nt + 2] - u[4 * nt + 2] - p1.x, z[4 * nt + 3] - u[4 * nt + 3] - p1.y, hi, lo);
            *(uint32_t*)(rhB + r1 * S136 + c) = hi;
            *(uint32_t*)(rlB + r1 * S136 + c) = lo;
        }
        __syncthreads();   // (iter 0: also covers W-tile load)

        float acc[8][4];
#pragma unroll
        for (int nt = 0; nt < 8; nt++)
#pragma unroll
            for (int j = 0; j < 4; j++) acc[nt][j] = 0.0f;
#pragma unroll
        for (int k0 = 0; k0 < 8; k0++) {
            int ka = k0 * 16 + 2 * tig;
            uint32_t ah0 = *(uint32_t*)(rhB + r0 * S136 + ka);
            uint32_t ah1 = *(uint32_t*)(rhB + r1 * S136 + ka);
            uint32_t ah2 = *(uint32_t*)(rhB + r0 * S136 + ka + 8);
            uint32_t ah3 = *(uint32_t*)(rhB + r1 * S136 + ka + 8);
            uint32_t al0 = *(uint32_t*)(rlB + r0 * S136 + ka);
            uint32_t al1 = *(uint32_t*)(rlB + r1 * S136 + ka);
            uint32_t al2 = *(uint32_t*)(rlB + r0 * S136 + ka + 8);
            uint32_t al3 = *(uint32_t*)(rlB + r1 * S136 + ka + 8);
#pragma unroll
            for (int nt = 0; nt < 8; nt++) {
                int bn = n0 + nt * 8 + gid;
                uint32_t b0 = *(uint32_t*)(w1B + bn * S136 + ka);
                uint32_t b1 = *(uint32_t*)(w1B + bn * S136 + ka + 8);
                mma_bf16(acc[nt], ah0, ah1, ah2, ah3, b0, b1);
                mma_bf16(acc[nt], al0, al1, al2, al3, b0, b1);
                uint32_t c0 = *(uint32_t*)(w2B + bn * S136 + ka);
                uint32_t c1 = *(uint32_t*)(w2B + bn * S136 + ka + 8);
                mma_bf16(acc[nt], ah0, ah1, ah2, ah3, c0, c1);
            }
        }
        __syncthreads();   // tile reads done before next-iter writes

        // pointwise: x = rhs + W*rhs; z,u updates (registers only)
#pragma unroll
        for (int nt = 0; nt < 8; nt++) {
            int c = n0 + nt * 8 + 2 * tig;
            float2 p0 = *(float2*)(sP + r0 * 132 + c);
            float2 p1 = *(float2*)(sP + r1 * 132 + c);
            float pv[4] = {p0.x, p0.y, p1.x, p1.y};
#pragma unroll
            for (int j = 0; j < 4; j++) {
                int e = 4 * nt + j;
                float rhs = z[e] - u[e] - pv[j];
                float x = rhs + acc[nt][j];
                float xu = x + u[e];
                float zn = fminf(fmaxf(xu, 0.0f), 1.0f);
                u[e] = xu - zn;
                z[e] = zn;
            }
        }
    }

    // ---- epilogue: counts, coeffs, out = coeff * (V/128) via 3-term MMA ----
    float cp0 = 0.0f, cp1 = 0.0f;
#pragma unroll
    for (int nt = 0; nt < 8; nt++) {
        cp0 += ((z[4 * nt]     > 0.5f) ? 1.0f : 0.0f) + ((z[4 * nt + 1] > 0.5f) ? 1.0f : 0.0f);
        cp1 += ((z[4 * nt + 2] > 0.5f) ? 1.0f : 0.0f) + ((z[4 * nt + 3] > 0.5f) ? 1.0f : 0.0f);
    }
    sCnt[r0 * 8 + (w >> 3) * 4 + tig] = cp0;
    sCnt[r1 * 8 + (w >> 3) * 4 + tig] = cp1;
    __syncthreads();
    float c0s = 0.0f, c1s = 0.0f;
#pragma unroll
    for (int k = 0; k < 8; k++) { c0s += sCnt[r0 * 8 + k]; c1s += sCnt[r1 * 8 + k]; }
    float inv0 = 1.0f / (128.0f * (c0s + 1e-10f));
    float inv1 = 1.0f / (128.0f * (c1s + 1e-10f));

    // coeff split into rhs tiles
#pragma unroll
    for (int nt = 0; nt < 8; nt++) {
        int c = n0 + nt * 8 + 2 * tig;
        uint32_t hi, lo;
        split2((z[4 * nt]     > 0.5f) ? inv0 : 0.0f,
               (z[4 * nt + 1] > 0.5f) ? inv0 : 0.0f, hi, lo);
        *(uint32_t*)(rhB + r0 * S136 + c) = hi;
        *(uint32_t*)(rlB + r0 * S136 + c) = lo;
        split2((z[4 * nt + 2] > 0.5f) ? inv1 : 0.0f,
               (z[4 * nt + 3] > 0.5f) ? inv1 : 0.0f, hi, lo);
        *(uint32_t*)(rhB + r1 * S136 + c) = hi;
        *(uint32_t*)(rlB + r1 * S136 + c) = lo;
    }
    // Vt split into W tiles: tile[d][m] = V[m][d]
    for (int idx = t; idx < 16384; idx += 512) {
        int m = idx >> 7, d = idx & 127;
        float f = Vb[idx];
        __nv_bfloat16 h = __float2bfloat16(f);
        w1B[d * S136 + m] = h;
        w2B[d * S136 + m] = __float2bfloat16(f - __bfloat162float(h));
    }
    __syncthreads();

    {
        float acc[8][4];
#pragma unroll
        for (int nt = 0; nt < 8; nt++)
#pragma unroll
            for (int j = 0; j < 4; j++) acc[nt][j] = 0.0f;
#pragma unroll
        for (int k0 = 0; k0 < 8; k0++) {
            int ka = k0 * 16 + 2 * tig;
            uint32_t ah0 = *(uint32_t*)(rhB + r0 * S136 + ka);
            uint32_t ah1 = *(uint32_t*)(rhB + r1 * S136 + ka);
            uint32_t ah2 = *(uint32_t*)(rhB + r0 * S136 + ka + 8);
            uint32_t ah3 = *(uint32_t*)(rhB + r1 * S136 + ka + 8);
            uint32_t al0 = *(uint32_t*)(rlB + r0 * S136 + ka);
            uint32_t al1 = *(uint32_t*)(rlB + r1 * S136 + ka);
            uint32_t al2 = *(uint32_t*)(rlB + r0 * S136 + ka + 8);
            uint32_t al3 = *(uint32_t*)(rlB + r1 * S136 + ka + 8);
#pragma unroll
            for (int nt = 0; nt < 8; nt++) {
                int bn = n0 + nt * 8 + gid;
                uint32_t b0 = *(uint32_t*)(w1B + bn * S136 + ka);
                uint32_t b1 = *(uint32_t*)(w1B + bn * S136 + ka + 8);
                mma_bf16(acc[nt], ah0, ah1, ah2, ah3, b0, b1);
                mma_bf16(acc[nt], al0, al1, al2, al3, b0, b1);
                uint32_t c0 = *(uint32_t*)(w2B + bn * S136 + ka);
                uint32_t c1 = *(uint32_t*)(w2B + bn * S136 + ka + 8);
                mma_bf16(acc[nt], ah0, ah1, ah2, ah3, c0, c1);
            }
        }
        float* ob = gOut + (size_t)(b * NN + row0) * 128;
#pragma unroll
        for (int nt = 0; nt < 8; nt++) {
            int c = n0 + nt * 8 + 2 * tig;
            *(float2*)(ob + r0 * 128 + c) = make_float2(acc[nt][0], acc[nt][1]);
            *(float2*)(ob + r1 * 128 + c) = make_float2(acc[nt][2], acc[nt][3]);
        }
    }
}

// ============================================================================

extern "C" void kernel_launch(void* const* d_in, const int* in_sizes, int n_in,
                              void* d_out, int out_size) {
    const float* gQ = (const float*)d_in[0];
    const float* gV = (const float*)d_in[1];
    if (n_in >= 2 && in_sizes[0] == BB * 128 * 128 && in_sizes[1] == BB * NN * 128) {
        gV = (const float*)d_in[0];
        gQ = (const float*)d_in[1];
    }
    float* out = (float*)d_out;

    const int SMEM_E  = 128 * 132 * 4;                 // 67584
    const int SMEM_MM = (32 * 129 + 128 * 128) * 4;    // 82048

    cudaFuncSetAttribute(kE,  cudaFuncAttributeMaxDynamicSharedMemorySize, SMEM_E);
    cudaFuncSetAttribute(kMM, cudaFuncAttributeMaxDynamicSharedMemorySize, SMEM_MM);
    cudaFuncSetAttribute(kW,  cudaFuncAttributeMaxDynamicSharedMemorySize, SMEM_MM);
    cudaFuncSetAttribute(k_admm, cudaFuncAttributeMaxDynamicSharedMemorySize, SMEM_ADMM);

    void* pe;  cudaGetSymbolAddress(&pe,  gE);
    void* pe2; cudaGetSymbolAddress(&pe2, gE2);
    void* pe4; cudaGetSymbolAddress(&pe4, gE4);
    void* ptt; cudaGetSymbolAddress(&ptt, gTT);

    kE<<<32, 256, SMEM_E>>>(gV);
    kMM<<<32, 256, SMEM_MM>>>((const float*)pe,  (const float*)pe,  (float*)pe2, 0); // E2 = E*E
    kMM<<<32, 256, SMEM_MM>>>((const float*)pe2, (const float*)pe2, (float*)pe4, 0); // E4 = E2*E2
    kMM<<<32, 256, SMEM_MM>>>((const float*)pe2, (const float*)pe4, (float*)ptt, 1); // TT = E2+E4+E6
    kW<<<32, 256, SMEM_MM>>>();                                                      // W -> gW1/gW2
    k_admm<<<BB * (NN / 128), 512, SMEM_ADMM>>>(gQ, gV, out);
}

// round 6
// speedup vs baseline: 4.0323x; 1.1055x over previous
#include <cuda_runtime.h>
#include <cuda_bf16.h>
#include <cstdint>

#define BB 8
#define NN 2048
#define ITERS 50

// ---- device scratch (no allocs allowed) ----
__device__ float gE[BB * 16384], gE2[BB * 16384], gE4[BB * 16384], gTT[BB * 16384];
__device__ __nv_bfloat16 gW1[BB * 16384], gW2[BB * 16384];

// ---- f32x2 helpers (prep kernels) ----
__device__ __forceinline__ unsigned long long ffma2(unsigned long long a,
                                                    unsigned long long b,
                                                    unsigned long long c) {
    unsigned long long d;
    asm("fma.rn.f32x2 %0, %1, %2, %3;" : "=l"(d) : "l"(a), "l"(b), "l"(c));
    return d;
}
__device__ __forceinline__ unsigned long long pack2(float x) {
    union { unsigned long long u; float2 f; } c; c.f = make_float2(x, x); return c.u;
}
__device__ __forceinline__ float2 unpack2(unsigned long long v) {
    union { unsigned long long u; float2 f; } c; c.u = v; return c.f;
}

// ---- HMMA m16n8k16 bf16 -> f32 ----
__device__ __forceinline__ void mma_bf16(float c[4],
                                         uint32_t a0, uint32_t a1, uint32_t a2, uint32_t a3,
                                         uint32_t b0, uint32_t b1) {
    asm volatile(
        "mma.sync.aligned.m16n8k16.row.col.f32.bf16.bf16.f32 "
        "{%0,%1,%2,%3}, {%4,%5,%6,%7}, {%8,%9}, {%0,%1,%2,%3};"
        : "+f"(c[0]), "+f"(c[1]), "+f"(c[2]), "+f"(c[3])
        : "r"(a0), "r"(a1), "r"(a2), "r"(a3), "r"(b0), "r"(b1));
}

__device__ __forceinline__ void split2(float x, float y, uint32_t& hi, uint32_t& lo) {
    __nv_bfloat162 h = __float22bfloat162_rn(make_float2(x, y));
    float2 hb = __bfloat1622float2(h);
    __nv_bfloat162 l = __float22bfloat162_rn(make_float2(x - hb.x, y - hb.y));
    hi = *(uint32_t*)&h;
    lo = *(uint32_t*)&l;
}

__device__ __forceinline__ void barg(int id) {
    asm volatile("bar.sync %0, %1;" :: "r"(id), "r"(256) : "memory");
}

// ============================================================================
// kE: E = (1/8192) V V^T.  grid 64 (b*8 + 16-row slice) x 256 thr.
// Per thread: row r, 8 cols (4 ffma2 pairs) -- same even/odd pairing + d-order
// as before (bit-identical per element).
// ============================================================================
__global__ __launch_bounds__(256, 1) void kE(const float* __restrict__ gV) {
    extern __shared__ float sm[];
    float* sVt = sm;                         // [128][132]
    const int b = blockIdx.x >> 3, r0 = (blockIdx.x & 7) * 16;
    const int t = threadIdx.x;
    for (int idx = t; idx < 16384; idx += 256) {
        int m = idx >> 7, d = idx & 127;
        sVt[d * 132 + m] = gV[b * 16384 + idx];
    }
    __syncthreads();
    const int r = r0 + (t & 15), i0 = (t >> 4) * 8;
    unsigned long long acc[4];
#pragma unroll
    for (int e = 0; e < 4; e++) acc[e] = 0ULL;
#pragma unroll 8
    for (int d = 0; d < 128; d++) {
        unsigned long long a2 = pack2(sVt[d * 132 + r]);
        const ulonglong2* pm = (const ulonglong2*)(sVt + d * 132 + i0);
        ulonglong2 m0 = pm[0], m1 = pm[1];
        acc[0] = ffma2(m0.x, a2, acc[0]);
        acc[1] = ffma2(m0.y, a2, acc[1]);
        acc[2] = ffma2(m1.x, a2, acc[2]);
        acc[3] = ffma2(m1.y, a2, acc[3]);
    }
    const float sc = 1.0f / 8192.0f;
#pragma unroll
    for (int e = 0; e < 4; e++) {
        float2 v = unpack2(acc[e]);
        gE[b * 16384 + r * 128 + i0 + 2 * e]     = sc * v.x;
        gE[b * 16384 + r * 128 + i0 + 2 * e + 1] = sc * v.y;
    }
}

// ============================================================================
// kMM: C = A*B (+A+B if mode).  grid 128 (b*16 + 8-row slice) x 256 thr.
// Per thread: row r, 4 cols (2 ffma2 pairs), j-order preserved.
// ============================================================================
__global__ __launch_bounds__(256, 1) void kMM(const float* __restrict__ A,
                                              const float* __restrict__ B,
                                              float* __restrict__ C, int mode) {
    extern __shared__ float sm[];
    float* sA = sm;                 // [8][129]
    float* sB = sm + 8 * 129;       // [128][128]
    const int b = blockIdx.x >> 4, r0 = (blockIdx.x & 15) * 8;
    const int t = threadIdx.x;
    for (int idx = t; idx < 1024; idx += 256) {
        int row = idx >> 7, j = idx & 127;
        sA[row * 129 + j] = A[b * 16384 + (r0 + row) * 128 + j];
    }
    for (int idx = t; idx < 4096; idx += 256)
        ((float4*)sB)[idx] = ((const float4*)(B + b * 16384))[idx];
    __syncthreads();
    const int rl = t & 7, r = r0 + rl, i0 = (t >> 3) * 4;
    unsigned long long acc[2];
    acc[0] = 0ULL; acc[1] = 0ULL;
#pragma unroll 8
    for (int j = 0; j < 128; j++) {
        unsigned long long a2 = pack2(sA[rl * 129 + j]);
        ulonglong2 mv = *(const ulonglong2*)(sB + j * 128 + i0);
        acc[0] = ffma2(mv.x, a2, acc[0]);
        acc[1] = ffma2(mv.y, a2, acc[1]);
    }
#pragma unroll
    for (int e = 0; e < 2; e++) {
        float2 v = unpack2(acc[e]);
        int c0 = i0 + 2 * e;
        float o0 = v.x, o1 = v.y;
        if (mode) {
            o0 += sA[rl * 129 + c0]     + sB[r * 128 + c0];
            o1 += sA[rl * 129 + c0 + 1] + sB[r * 128 + c0 + 1];
        }
        C[b * 16384 + r * 128 + c0]     = o0;
        C[b * 16384 + r * 128 + c0 + 1] = o1;
    }
}

// ============================================================================
// kW: W = TT - E - E*TT; bf16 hi/lo row-major.  grid 128 x 256.
// ============================================================================
__global__ __launch_bounds__(256, 1) void kW() {
    extern __shared__ float sm[];
    float* sA = sm;                 // E slice [8][129]
    float* sB = sm + 8 * 129;       // TT [128][128]
    const int b = blockIdx.x >> 4, r0 = (blockIdx.x & 15) * 8;
    const int t = threadIdx.x;
    for (int idx = t; idx < 1024; idx += 256) {
        int row = idx >> 7, j = idx & 127;
        sA[row * 129 + j] = gE[b * 16384 + (r0 + row) * 128 + j];
    }
    for (int idx = t; idx < 4096; idx += 256)
        ((float4*)sB)[idx] = ((const float4*)(gTT + b * 16384))[idx];
    __syncthreads();
    const int rl = t & 7, r = r0 + rl, k0 = (t >> 3) * 4;
    unsigned long long acc[2];
    acc[0] = 0ULL; acc[1] = 0ULL;
#pragma unroll 8
    for (int j = 0; j < 128; j++) {
        unsigned long long a2 = pack2(sA[rl * 129 + j]);
        ulonglong2 mv = *(const ulonglong2*)(sB + j * 128 + k0);
        acc[0] = ffma2(mv.x, a2, acc[0]);
        acc[1] = ffma2(mv.y, a2, acc[1]);
    }
    uint32_t* o1 = (uint32_t*)gW1 + b * 8192;
    uint32_t* o2 = (uint32_t*)gW2 + b * 8192;
#pragma unroll
    for (int e = 0; e < 2; e++) {
        float2 m1 = unpack2(acc[e]);
        int k = k0 + 2 * e;
        float wx = sB[r * 128 + k]     - sA[rl * 129 + k]     - m1.x;
        float wy = sB[r * 128 + k + 1] - sA[rl * 129 + k + 1] - m1.y;
        uint32_t hi, lo;
        split2(wx, wy, hi, lo);
        o1[r * 64 + (k >> 1)] = hi;
        o2[r * 64 + (k >> 1)] = lo;
    }
}

// ============================================================================
// k_admm: fused P-prep + 50 HMMA ADMM iters + epilogue.
// 512 thr = 2 independent groups of 256 (rows 64g..64g+63), named barriers.
// Warp tile (32,32): wg=w&7 -> mg=wg&1 (32-row block), ng=wg>>1 (32-col block).
// Per-element MMA term order unchanged: k0 asc, (Ah*W1, Al*W1, Ah*W2).
// ============================================================================
#define S136 136
#define SM_RH 0                  // rhs hi [128][136] bf16
#define SM_RL 34816
#define SM_W1 69632              // W hi (V in prologue, Vt in epilogue)
#define SM_W2 104448
#define SM_P  139264             // f32 [128][132]
#define SM_CNT 206848            // f32 [128][16]
#define SMEM_ADMM 215040

__global__ __launch_bounds__(512, 1) void k_admm(const float* __restrict__ gQ,
                                                 const float* __restrict__ gV,
                                                 float* __restrict__ gOut) {
    extern __shared__ char smem[];
    __nv_bfloat16* rhB = (__nv_bfloat16*)(smem + SM_RH);
    __nv_bfloat16* rlB = (__nv_bfloat16*)(smem + SM_RL);
    __nv_bfloat16* w1B = (__nv_bfloat16*)(smem + SM_W1);
    __nv_bfloat16* w2B = (__nv_bfloat16*)(smem + SM_W2);
    float* sP   = (float*)(smem + SM_P);
    float* sCnt = (float*)(smem + SM_CNT);

    const int t = threadIdx.x;
    const int lane = t & 31, w = t >> 5;
    const int g = w >> 3, wg = w & 7;
    const int mg = wg & 1, ng = wg >> 1;
    const int gid = lane >> 2, tig = lane & 3;
    const int m0 = g * 64 + mg * 32, n0 = ng * 32;
    const int rA = m0 + gid;              // mt row bases: rA+16*mt, +8
    const int b = blockIdx.x >> 4, row0 = (blockIdx.x & 15) * 128;
    const float* Vb = gV + b * 16384;
    const float* Qb = gQ + (size_t)(b * NN + row0) * 128;

    // ---- prologue: Q split -> rhs tiles; V split -> W tiles ----
    for (int idx = t; idx < 8192; idx += 512) {
        int row = idx >> 6, c2 = (idx & 63) * 2;
        float2 q = *(const float2*)(Qb + row * 128 + c2);
        uint32_t hi, lo;
        split2(q.x, q.y, hi, lo);
        *(uint32_t*)(rhB + row * S136 + c2) = hi;
        *(uint32_t*)(rlB + row * S136 + c2) = lo;
        float2 v = *(const float2*)(Vb + row * 128 + c2);
        split2(v.x, v.y, hi, lo);
        *(uint32_t*)(w1B + row * S136 + c2) = hi;
        *(uint32_t*)(w2B + row * S136 + c2) = lo;
    }
    __syncthreads();

    // ---- P = -(2/m) Q V^T + lambda/m (group-local 3-term MMA) ----
    {
        float acc[2][4][4];
#pragma unroll
        for (int mt = 0; mt < 2; mt++)
#pragma unroll
            for (int nt = 0; nt < 4; nt++)
#pragma unroll
                for (int j = 0; j < 4; j++) acc[mt][nt][j] = 0.0f;
#pragma unroll
        for (int k0 = 0; k0 < 8; k0++) {
            int ka = k0 * 16 + 2 * tig;
            uint32_t ah[2][4], al[2][4];
#pragma unroll
            for (int mt = 0; mt < 2; mt++) {
                int ra = rA + 16 * mt, rb = ra + 8;
                ah[mt][0] = *(uint32_t*)(rhB + ra * S136 + ka);
                ah[mt][1] = *(uint32_t*)(rhB + rb * S136 + ka);
                ah[mt][2] = *(uint32_t*)(rhB + ra * S136 + ka + 8);
                ah[mt][3] = *(uint32_t*)(rhB + rb * S136 + ka + 8);
                al[mt][0] = *(uint32_t*)(rlB + ra * S136 + ka);
                al[mt][1] = *(uint32_t*)(rlB + rb * S136 + ka);
                al[mt][2] = *(uint32_t*)(rlB + ra * S136 + ka + 8);
                al[mt][3] = *(uint32_t*)(rlB + rb * S136 + ka + 8);
            }
#pragma unroll
            for (int nt = 0; nt < 4; nt++) {
                int bn = n0 + nt * 8 + gid;
                uint32_t b0 = *(uint32_t*)(w1B + bn * S136 + ka);
                uint32_t b1 = *(uint32_t*)(w1B + bn * S136 + ka + 8);
                uint32_t c0 = *(uint32_t*)(w2B + bn * S136 + ka);
                uint32_t c1 = *(uint32_t*)(w2B + bn * S136 + ka + 8);
#pragma unroll
                for (int mt = 0; mt < 2; mt++) {
                    mma_bf16(acc[mt][nt], ah[mt][0], ah[mt][1], ah[mt][2], ah[mt][3], b0, b1);
                    mma_bf16(acc[mt][nt], al[mt][0], al[mt][1], al[mt][2], al[mt][3], b0, b1);
                    mma_bf16(acc[mt][nt], ah[mt][0], ah[mt][1], ah[mt][2], ah[mt][3], c0, c1);
                }
            }
        }
        const float cP = -2.0f / 128.0f, cL = 0.1f / 128.0f;
#pragma unroll
        for (int mt = 0; mt < 2; mt++) {
            int ra = rA + 16 * mt, rb = ra + 8;
#pragma unroll
            for (int nt = 0; nt < 4; nt++) {
                int c = n0 + nt * 8 + 2 * tig;
                *(float2*)(sP + ra * 132 + c) = make_float2(cP * acc[mt][nt][0] + cL, cP * acc[mt][nt][1] + cL);
                *(float2*)(sP + rb * 132 + c) = make_float2(cP * acc[mt][nt][2] + cL, cP * acc[mt][nt][3] + cL);
            }
        }
    }
    __syncthreads();   // V-tile reads done

    // ---- load W bf16 hi/lo ----
    {
        const uint32_t* w1g = (const uint32_t*)gW1 + b * 8192;
        const uint32_t* w2g = (const uint32_t*)gW2 + b * 8192;
        for (int idx = t; idx < 8192; idx += 512) {
            int row = idx >> 6, cw = idx & 63;
            *(uint32_t*)(w1B + row * S136 + cw * 2) = w1g[row * 64 + cw];
            *(uint32_t*)(w2B + row * S136 + cw * 2) = w2g[row * 64 + cw];
        }
    }
    __syncthreads();

    float z[32], u[32];
#pragma unroll
    for (int e = 0; e < 32; e++) { z[e] = 0.0f; u[e] = 0.0f; }

    // ---- 50 ADMM iterations (group-synchronized) ----
    for (int it = 0; it < ITERS; it++) {
#pragma unroll
        for (int mt = 0; mt < 2; mt++) {
            int ra = rA + 16 * mt, rb = ra + 8;
#pragma unroll
            for (int nt = 0; nt < 4; nt++) {
                int e = mt * 16 + nt * 4;
                int c = n0 + nt * 8 + 2 * tig;
                float2 p0 = *(float2*)(sP + ra * 132 + c);
                float2 p1 = *(float2*)(sP + rb * 132 + c);
                uint32_t hi, lo;
                split2(z[e] - u[e] - p0.x, z[e + 1] - u[e + 1] - p0.y, hi, lo);
                *(uint32_t*)(rhB + ra * S136 + c) = hi;
                *(uint32_t*)(rlB + ra * S136 + c) = lo;
                split2(z[e + 2] - u[e + 2] - p1.x, z[e + 3] - u[e + 3] - p1.y, hi, lo);
                *(uint32_t*)(rhB + rb * S136 + c) = hi;
                *(uint32_t*)(rlB + rb * S136 + c) = lo;
            }
        }
        barg(1 + g);

        float acc[2][4][4];
#pragma unroll
        for (int mt = 0; mt < 2; mt++)
#pragma unroll
            for (int nt = 0; nt < 4; nt++)
#pragma unroll
                for (int j = 0; j < 4; j++) acc[mt][nt][j] = 0.0f;
#pragma unroll
        for (int k0 = 0; k0 < 8; k0++) {
            int ka = k0 * 16 + 2 * tig;
            uint32_t ah[2][4], al[2][4];
#pragma unroll
            for (int mt = 0; mt < 2; mt++) {
                int ra = rA + 16 * mt, rb = ra + 8;
                ah[mt][0] = *(uint32_t*)(rhB + ra * S136 + ka);
                ah[mt][1] = *(uint32_t*)(rhB + rb * S136 + ka);
                ah[mt][2] = *(uint32_t*)(rhB + ra * S136 + ka + 8);
                ah[mt][3] = *(uint32_t*)(rhB + rb * S136 + ka + 8);
                al[mt][0] = *(uint32_t*)(rlB + ra * S136 + ka);
                al[mt][1] = *(uint32_t*)(rlB + rb * S136 + ka);
                al[mt][2] = *(uint32_t*)(rlB + ra * S136 + ka + 8);
                al[mt][3] = *(uint32_t*)(rlB + rb * S136 + ka + 8);
            }
#pragma unroll
            for (int nt = 0; nt < 4; nt++) {
                int bn = n0 + nt * 8 + gid;
                uint32_t b0 = *(uint32_t*)(w1B + bn * S136 + ka);
                uint32_t b1 = *(uint32_t*)(w1B + bn * S136 + ka + 8);
                uint32_t c0 = *(uint32_t*)(w2B + bn * S136 + ka);
                uint32_t c1 = *(uint32_t*)(w2B + bn * S136 + ka + 8);
#pragma unroll
                for (int mt = 0; mt < 2; mt++) {
                    mma_bf16(acc[mt][nt], ah[mt][0], ah[mt][1], ah[mt][2], ah[mt][3], b0, b1);
                    mma_bf16(acc[mt][nt], al[mt][0], al[mt][1], al[mt][2], al[mt][3], b0, b1);
                    mma_bf16(acc[mt][nt], ah[mt][0], ah[mt][1], ah[mt][2], ah[mt][3], c0, c1);
                }
            }
        }
        barg(1 + g);

#pragma unroll
        for (int mt = 0; mt < 2; mt++) {
            int ra = rA + 16 * mt, rb = ra + 8;
#pragma unroll
            for (int nt = 0; nt < 4; nt++) {
                int e = mt * 16 + nt * 4;
                int c = n0 + nt * 8 + 2 * tig;
                float2 p0 = *(float2*)(sP + ra * 132 + c);
                float2 p1 = *(float2*)(sP + rb * 132 + c);
                float pv[4] = {p0.x, p0.y, p1.x, p1.y};
#pragma unroll
                for (int j = 0; j < 4; j++) {
                    float rhs = z[e + j] - u[e + j] - pv[j];
                    float x = rhs + acc[mt][nt][j];
                    float xu = x + u[e + j];
                    float zn = fminf(fmaxf(xu, 0.0f), 1.0f);
                    u[e + j] = xu - zn;
                    z[e + j] = zn;
                }
            }
        }
    }

    // ---- epilogue ----
#pragma unroll
    for (int mt = 0; mt < 2; mt++) {
        int ra = rA + 16 * mt, rb = ra + 8;
        float c0s = 0.0f, c1s = 0.0f;
#pragma unroll
        for (int nt = 0; nt < 4; nt++) {
            int e = mt * 16 + nt * 4;
            c0s += ((z[e]     > 0.5f) ? 1.0f : 0.0f) + ((z[e + 1] > 0.5f) ? 1.0f : 0.0f);
            c1s += ((z[e + 2] > 0.5f) ? 1.0f : 0.0f) + ((z[e + 3] > 0.5f) ? 1.0f : 0.0f);
        }
        sCnt[ra * 16 + ng * 4 + tig] = c0s;
        sCnt[rb * 16 + ng * 4 + tig] = c1s;
    }
    barg(1 + g);
    float inv[2][2];
#pragma unroll
    for (int mt = 0; mt < 2; mt++) {
        int ra = rA + 16 * mt, rb = ra + 8;
        float s0 = 0.0f, s1 = 0.0f;
#pragma unroll
        for (int k = 0; k < 16; k++) { s0 += sCnt[ra * 16 + k]; s1 += sCnt[rb * 16 + k]; }
        inv[mt][0] = 1.0f / (128.0f * (s0 + 1e-10f));
        inv[mt][1] = 1.0f / (128.0f * (s1 + 1e-10f));
    }
#pragma unroll
    for (int mt = 0; mt < 2; mt++) {
        int ra = rA + 16 * mt, rb = ra + 8;
#pragma unroll
        for (int nt = 0; nt < 4; nt++) {
            int e = mt * 16 + nt * 4;
            int c = n0 + nt * 8 + 2 * tig;
            uint32_t hi, lo;
            split2((z[e]     > 0.5f) ? inv[mt][0] : 0.0f,
                   (z[e + 1] > 0.5f) ? inv[mt][0] : 0.0f, hi, lo);
            *(uint32_t*)(rhB + ra * S136 + c) = hi;
            *(uint32_t*)(rlB + ra * S136 + c) = lo;
            split2((z[e + 2] > 0.5f) ? inv[mt][1] : 0.0f,
                   (z[e + 3] > 0.5f) ? inv[mt][1] : 0.0f, hi, lo);
            *(uint32_t*)(rhB + rb * S136 + c) = hi;
            *(uint32_t*)(rlB + rb * S136 + c) = lo;
        }
    }
    __syncthreads();   // both groups done with W tiles + coeff writes
    for (int idx = t; idx < 16384; idx += 512) {
        int m = idx >> 7, d = idx & 127;
        float f = Vb[idx];
        __nv_bfloat16 h = __float2bfloat16(f);
        w1B[d * S136 + m] = h;
        w2B[d * S136 + m] = __float2bfloat16(f - __bfloat162float(h));
    }
    __syncthreads();

    {
        float acc[2][4][4];
#pragma unroll
        for (int mt = 0; mt < 2; mt++)
#pragma unroll
            for (int nt = 0; nt < 4; nt++)
#pragma unroll
                for (int j = 0; j < 4; j++) acc[mt][nt][j] = 0.0f;
#pragma unroll
        for (int k0 = 0; k0 < 8; k0++) {
            int ka = k0 * 16 + 2 * tig;
            uint32_t ah[2][4], al[2][4];
#pragma unroll
            for (int mt = 0; mt < 2; mt++) {
                int ra = rA + 16 * mt, rb = ra + 8;
                ah[mt][0] = *(uint32_t*)(rhB + ra * S136 + ka);
                ah[mt][1] = *(uint32_t*)(rhB + rb * S136 + ka);
                ah[mt][2] = *(uint32_t*)(rhB + ra * S136 + ka + 8);
                ah[mt][3] = *(uint32_t*)(rhB + rb * S136 + ka + 8);
                al[mt][0] = *(uint32_t*)(rlB + ra * S136 + ka);
                al[mt][1] = *(uint32_t*)(rlB + rb * S136 + ka);
                al[mt][2] = *(uint32_t*)(rlB + ra * S136 + ka + 8);
                al[mt][3] = *(uint32_t*)(rlB + rb * S136 + ka + 8);
            }
#pragma unroll
            for (int nt = 0; nt < 4; nt++) {
                int bn = n0 + nt * 8 + gid;
                uint32_t b0 = *(uint32_t*)(w1B + bn * S136 + ka);
                uint32_t b1 = *(uint32_t*)(w1B + bn * S136 + ka + 8);
                uint32_t c0 = *(uint32_t*)(w2B + bn * S136 + ka);
                uint32_t c1 = *(uint32_t*)(w2B + bn * S136 + ka + 8);
#pragma unroll
                for (int mt = 0; mt < 2; mt++) {
                    mma_bf16(acc[mt][nt], ah[mt][0], ah[mt][1], ah[mt][2], ah[mt][3], b0, b1);
                    mma_bf16(acc[mt][nt], al[mt][0], al[mt][1], al[mt][2], al[mt][3], b0, b1);
                    mma_bf16(acc[mt][nt], ah[mt][0], ah[mt][1], ah[mt][2], ah[mt][3], c0, c1);
                }
            }
        }
        float* ob = gOut + (size_t)(b * NN + row0) * 128;
#pragma unroll
        for (int mt = 0; mt < 2; mt++) {
            int ra = rA + 16 * mt, rb = ra + 8;
#pragma unroll
            for (int nt = 0; nt < 4; nt++) {
                int c = n0 + nt * 8 + 2 * tig;
                *(float2*)(ob + ra * 128 + c) = make_float2(acc[mt][nt][0], acc[mt][nt][1]);
                *(float2*)(ob + rb * 128 + c) = make_float2(acc[mt][nt][2], acc[mt][nt][3]);
            }
        }
    }
}

// ============================================================================

extern "C" void kernel_launch(void* const* d_in, const int* in_sizes, int n_in,
                              void* d_out, int out_size) {
    const float* gQ = (const float*)d_in[0];
    const float* gV = (const float*)d_in[1];
    if (n_in >= 2 && in_sizes[0] == BB * 128 * 128 && in_sizes[1] == BB * NN * 128) {
        gV = (const float*)d_in[0];
        gQ = (const float*)d_in[1];
    }
    float* out = (float*)d_out;

    const int SMEM_E  = 128 * 132 * 4;                 // 67584
    const int SMEM_MM = (8 * 129 + 128 * 128) * 4;     // 69664

    cudaFuncSetAttribute(kE,  cudaFuncAttributeMaxDynamicSharedMemorySize, SMEM_E);
    cudaFuncSetAttribute(kMM, cudaFuncAttributeMaxDynamicSharedMemorySize, SMEM_MM);
    cudaFuncSetAttribute(kW,  cudaFuncAttributeMaxDynamicSharedMemorySize, SMEM_MM);
    cudaFuncSetAttribute(k_admm, cudaFuncAttributeMaxDynamicSharedMemorySize, SMEM_ADMM);

    void* pe;  cudaGetSymbolAddress(&pe,  gE);
    void* pe2; cudaGetSymbolAddress(&pe2, gE2);
    void* pe4; cudaGetSymbolAddress(&pe4, gE4);
    void* ptt; cudaGetSymbolAddress(&ptt, gTT);

    kE<<<64, 256, SMEM_E>>>(gV);
    kMM<<<128, 256, SMEM_MM>>>((const float*)pe,  (const float*)pe,  (float*)pe2, 0); // E2 = E*E
    kMM<<<128, 256, SMEM_MM>>>((const float*)pe2, (const float*)pe2, (float*)pe4, 0); // E4 = E2*E2
    kMM<<<128, 256, SMEM_MM>>>((const float*)pe2, (const float*)pe4, (float*)ptt, 1); // TT = E2+E4+E6
    kW<<<128, 256, SMEM_MM>>>();                                                      // W -> gW1/gW2
    k_admm<<<BB * (NN / 128), 512, SMEM_ADMM>>>(gQ, gV, out);
}